// round 8
// baseline (speedup 1.0000x reference)
#include <cuda_runtime.h>
#include <math.h>

#define BB 1024
#define CC 64
#define DD 256
#define NN 512
#define K2 (2*DD)
#define DELTA 1e-4f

__device__ float g_boost[CC*NN];

// ---------------------------------------------------------------------------
// Kernel 0: boost[c,n] = log1p(0.05/(avg+1e-6))   (batch-independent)
// ---------------------------------------------------------------------------
__global__ void boost_kernel(const float* __restrict__ avg) {
    int i = blockIdx.x * blockDim.x + threadIdx.x;
    if (i < CC * NN) g_boost[i] = log1pf(0.05f / (avg[i] + 1e-6f));
}

// ---- tf32 split: (hi = rna-tf32(x), lo = x - hi) ----
__device__ __forceinline__ float2 split1(float f) {
    unsigned h;
    asm("cvt.rna.tf32.f32 %0, %1;" : "=r"(h) : "f"(f));
    float hf = __uint_as_float(h);
    return make_float2(hf, f - hf);
}
__device__ __forceinline__ void mma_tf32(
    float& c0, float& c1, float& c2, float& c3,
    unsigned a0, unsigned a1, unsigned a2, unsigned a3,
    unsigned b0, unsigned b1)
{
    asm("mma.sync.aligned.m16n8k8.row.col.f32.tf32.tf32.f32 "
        "{%0,%1,%2,%3},{%4,%5,%6,%7},{%8,%9},{%0,%1,%2,%3};"
        : "+f"(c0), "+f"(c1), "+f"(c2), "+f"(c3)
        : "r"(a0), "r"(a1), "r"(a2), "r"(a3), "r"(b0), "r"(b1));
}

// ---------------------------------------------------------------------------
// Kernel 1: drive GEMM via 3xTF32, hi/lo pre-split into smem (float2),
// inner loop = pure LDS.64 + MMA. Block 128x128, BK=8, double-buffered.
// ---------------------------------------------------------------------------
__global__ __launch_bounds__(256) void drive_gemm(
    const float* __restrict__ x_in, const float* __restrict__ x_ctx,
    const float* __restrict__ Wff,  const float* __restrict__ Wctx,
    const float* __restrict__ bias, float* __restrict__ act)
{
    const int BK = 8, LD2 = 132;            // LD2 in float2 units (pad)
    __shared__ float2 As2[2][BK][LD2];      // (hi, lo)
    __shared__ float2 Bs2[2][BK][LD2];

    int c  = blockIdx.z;
    int m0 = blockIdx.y * 128;
    int n0 = blockIdx.x * 128;
    int tid  = threadIdx.x;
    int warp = tid >> 5, lane = tid & 31;
    int wm = (warp & 1) * 64;
    int wn = (warp >> 1) * 32;
    int ar = lane >> 2;
    int ac = lane & 3;

    // loader coordinates: A rows need 2 float4 each (8 k), B rows 32 float4
    int am  = tid >> 1, akq = (tid & 1) * 4;
    int bkk = tid >> 5, bnq = lane * 4;

    float acc[16][4];
    #pragma unroll
    for (int i = 0; i < 16; i++)
        #pragma unroll
        for (int j = 0; j < 4; j++) acc[i][j] = 0.f;

    const float* WffC  = Wff  + (size_t)c * DD * NN;
    const float* WctxC = Wctx + (size_t)c * DD * NN;

    // ---- preload k-tile 0 (ff half) ----
    {
        float4 v = *reinterpret_cast<const float4*>(x_in + (size_t)(m0 + am) * DD + akq);
        As2[0][akq+0][am] = split1(v.x);
        As2[0][akq+1][am] = split1(v.y);
        As2[0][akq+2][am] = split1(v.z);
        As2[0][akq+3][am] = split1(v.w);
        float4 wv = *reinterpret_cast<const float4*>(WffC + (size_t)bkk * NN + n0 + bnq);
        Bs2[0][bkk][bnq+0] = split1(wv.x);
        Bs2[0][bkk][bnq+1] = split1(wv.y);
        Bs2[0][bkk][bnq+2] = split1(wv.z);
        Bs2[0][bkk][bnq+3] = split1(wv.w);
    }
    __syncthreads();

    int cur = 0;
    for (int kt = 0; kt < K2 / BK; kt++) {
        float4 pa, pb;
        float  nscale = 1.0f;
        bool   has_next = (kt + 1 < K2 / BK);
        if (has_next) {
            int k0 = (kt + 1) * BK;
            const float* asrc = (k0 < DD) ? (x_in + k0) : (x_ctx + (k0 - DD));
            nscale = (k0 < DD) ? 1.0f : 0.3f;
            pa = *reinterpret_cast<const float4*>(asrc + (size_t)(m0 + am) * DD + akq);
            const float* wsrc = (k0 < DD) ? (WffC + (size_t)k0 * NN)
                                          : (WctxC + (size_t)(k0 - DD) * NN);
            pb = *reinterpret_cast<const float4*>(wsrc + (size_t)bkk * NN + n0 + bnq);
        }

        // ---- compute: one k8 step, pure LDS.64 + MMA ----
        unsigned bh[8], bl[8];
        #pragma unroll
        for (int sn = 0; sn < 4; sn++) {
            float2 b0 = Bs2[cur][ac    ][wn + sn * 8 + ar];
            float2 b1 = Bs2[cur][ac + 4][wn + sn * 8 + ar];
            bh[sn*2+0] = __float_as_uint(b0.x); bl[sn*2+0] = __float_as_uint(b0.y);
            bh[sn*2+1] = __float_as_uint(b1.x); bl[sn*2+1] = __float_as_uint(b1.y);
        }
        #pragma unroll
        for (int sm = 0; sm < 4; sm++) {
            int mb = wm + sm * 16;
            float2 A0 = As2[cur][ac    ][mb + ar];
            float2 A1 = As2[cur][ac    ][mb + ar + 8];
            float2 A2 = As2[cur][ac + 4][mb + ar];
            float2 A3 = As2[cur][ac + 4][mb + ar + 8];
            unsigned ah0 = __float_as_uint(A0.x), al0 = __float_as_uint(A0.y);
            unsigned ah1 = __float_as_uint(A1.x), al1 = __float_as_uint(A1.y);
            unsigned ah2 = __float_as_uint(A2.x), al2 = __float_as_uint(A2.y);
            unsigned ah3 = __float_as_uint(A3.x), al3 = __float_as_uint(A3.y);
            #pragma unroll
            for (int sn = 0; sn < 4; sn++) {
                float* cp = acc[sm * 4 + sn];
                mma_tf32(cp[0], cp[1], cp[2], cp[3],
                         ah0, ah1, ah2, ah3, bh[sn*2], bh[sn*2+1]);
                mma_tf32(cp[0], cp[1], cp[2], cp[3],
                         ah0, ah1, ah2, ah3, bl[sn*2], bl[sn*2+1]);
                mma_tf32(cp[0], cp[1], cp[2], cp[3],
                         al0, al1, al2, al3, bh[sn*2], bh[sn*2+1]);
            }
        }

        if (has_next) {
            int nxt = cur ^ 1;
            As2[nxt][akq+0][am] = split1(pa.x * nscale);
            As2[nxt][akq+1][am] = split1(pa.y * nscale);
            As2[nxt][akq+2][am] = split1(pa.z * nscale);
            As2[nxt][akq+3][am] = split1(pa.w * nscale);
            Bs2[nxt][bkk][bnq+0] = split1(pb.x);
            Bs2[nxt][bkk][bnq+1] = split1(pb.y);
            Bs2[nxt][bkk][bnq+2] = split1(pb.z);
            Bs2[nxt][bkk][bnq+3] = split1(pb.w);
            __syncthreads();
            cur = nxt;
        }
    }

    // ---- epilogue: + bias, scatter to act[b, c, n] ----
    const float* bc = bias + (size_t)c * NN;
    #pragma unroll
    for (int sm = 0; sm < 4; sm++) {
        #pragma unroll
        for (int sn = 0; sn < 4; sn++) {
            const float* cp = acc[sm * 4 + sn];
            int col = n0 + wn + sn * 8 + ac * 2;
            float bx = bc[col], by = bc[col + 1];
            int r0 = m0 + wm + sm * 16 + ar;
            float2 v0 = make_float2(cp[0] + bx, cp[1] + by);
            float2 v1 = make_float2(cp[2] + bx, cp[3] + by);
            *reinterpret_cast<float2*>(act + ((size_t)r0 * CC + c) * NN + col)       = v0;
            *reinterpret_cast<float2*>(act + ((size_t)(r0 + 8) * CC + c) * NN + col) = v1;
        }
    }
}

// ---------------------------------------------------------------------------
// Kernel 2: warp-per-row k-WTA with margin-exact selection + normalize +
//           sparse pred/err.  (round-7 design, unchanged)
// ---------------------------------------------------------------------------
__device__ __forceinline__ unsigned f2ord(float f) {
    unsigned u = __float_as_uint(f);
    return (u & 0x80000000u) ? ~u : (u | 0x80000000u);
}
__device__ __forceinline__ float ord2f(unsigned u) {
    unsigned v = (u & 0x80000000u) ? (u & 0x7FFFFFFFu) : ~u;
    return __uint_as_float(v);
}

__global__ __launch_bounds__(256) void topk_pred(
    const int* __restrict__ kptr, const float* __restrict__ x_in,
    const float* __restrict__ x_ctx,
    const float* __restrict__ Wff, const float* __restrict__ Wctx,
    const float* __restrict__ bias,
    const float* __restrict__ Wp,
    float* __restrict__ act, float* __restrict__ pred, float* __restrict__ err)
{
    int lane = threadIdx.x & 31;
    int w    = threadIdx.x >> 5;
    int row  = blockIdx.x * 8 + w;          // b*C + c
    int c = row & (CC - 1);
    int b = row >> 6;

    __shared__ float s_vv[8][64];
    __shared__ int   s_ii[8][64];
    __shared__ int   s_bi[8][32];
    __shared__ float s_be[8][32];
    __shared__ int   s_bf[8][32];

    const float4* arow = reinterpret_cast<const float4*>(act + (size_t)row * NN);
    const float4* brow = reinterpret_cast<const float4*>(g_boost + (size_t)c * NN);

    float    f[16];
    float    bf[16];
    unsigned u[16];
    #pragma unroll
    for (int i = 0; i < 4; i++) {
        float4 a  = arow[i * 32 + lane];
        float4 bo = brow[i * 32 + lane];
        f[i*4+0] = a.x; f[i*4+1] = a.y; f[i*4+2] = a.z; f[i*4+3] = a.w;
        bf[i*4+0] = a.x + bo.x; bf[i*4+1] = a.y + bo.y;
        bf[i*4+2] = a.z + bo.z; bf[i*4+3] = a.w + bo.w;
        #pragma unroll
        for (int q = 0; q < 4; q++) u[i*4+q] = f2ord(bf[i*4+q]);
    }

    int k = *kptr;

    unsigned lmax = 0;
    #pragma unroll
    for (int s = 0; s < 16; s++) lmax = max(lmax, u[s]);
    unsigned mx = lmax, lb = lmax;
    #pragma unroll
    for (int o = 16; o; o >>= 1) {
        mx = max(mx, __shfl_xor_sync(0xffffffffu, mx, o));
        lb = min(lb, __shfl_xor_sync(0xffffffffu, lb, o));
    }
    if (k > 32) lb = 0u;

    unsigned diff = mx ^ lb;
    unsigned T;
    int topbit;
    if (diff == 0u) { T = mx; topbit = -1; }
    else {
        topbit = 31 - __clz(diff);
        unsigned mask = (topbit == 31) ? 0xFFFFFFFFu : ((2u << topbit) - 1u);
        T = mx & ~mask;
    }
    for (int bit = topbit; bit >= 0; --bit) {
        unsigned cand = T | (1u << bit);
        int cnt = 0;
        #pragma unroll
        for (int s = 0; s < 16; s++) cnt += (u[s] >= cand) ? 1 : 0;
        #pragma unroll
        for (int o = 16; o; o >>= 1) cnt += __shfl_xor_sync(0xffffffffu, cnt, o);
        if (cnt >= k) T = cand;
    }
    float Tf = ord2f(T);
    float thi = Tf + DELTA, tlo = Tf - DELTA;

    int nhi = 0, nbo = 0;
    #pragma unroll
    for (int s = 0; s < 16; s++) {
        nhi += (bf[s] > thi) ? 1 : 0;
        nbo += (bf[s] >= tlo && bf[s] <= thi) ? 1 : 0;
    }
    #pragma unroll
    for (int o = 16; o; o >>= 1) {
        nhi += __shfl_xor_sync(0xffffffffu, nhi, o);
        nbo += __shfl_xor_sync(0xffffffffu, nbo, o);
    }
    int r = k - nhi;

    bool win[16];
    if (nbo == r || nbo > 32) {
        #pragma unroll
        for (int s = 0; s < 16; s++) win[s] = (bf[s] >= tlo);
        if (nbo > 32) {
            #pragma unroll
            for (int s = 0; s < 16; s++) win[s] = (u[s] >= T);
        }
    } else {
        int bpos[16];
        int base = 0;
        #pragma unroll
        for (int i = 0; i < 4; i++) {
            #pragma unroll
            for (int q = 0; q < 4; q++) {
                int s = i * 4 + q;
                bool isb = (bf[s] >= tlo && bf[s] <= thi);
                unsigned m = __ballot_sync(0xffffffffu, isb);
                bpos[s] = -1;
                if (isb) {
                    int pos = base + __popc(m & ((1u << lane) - 1u));
                    bpos[s] = pos;
                    s_bi[w][pos] = i * 128 + lane * 4 + q;
                }
                base += __popc(m);
            }
        }
        __syncwarp();
        int mcnt = base;
        const float* xi = x_in  + (size_t)b * DD;
        const float* xc = x_ctx + (size_t)b * DD;
        for (int e = 0; e < mcnt; e++) {
            int ncol = s_bi[w][e];
            const float* wf = Wff  + ((size_t)c * DD) * NN + ncol;
            const float* wc = Wctx + ((size_t)c * DD) * NN + ncol;
            float aff = 0.f, act2 = 0.f;
            #pragma unroll
            for (int t = 0; t < 8; t++) {
                int d = lane + t * 32;
                aff  = fmaf(xi[d], wf[(size_t)d * NN], aff);
                act2 = fmaf(xc[d], wc[(size_t)d * NN], act2);
            }
            #pragma unroll
            for (int o = 16; o; o >>= 1) {
                aff  += __shfl_xor_sync(0xffffffffu, aff,  o);
                act2 += __shfl_xor_sync(0xffffffffu, act2, o);
            }
            if (lane == 0)
                s_be[w][e] = aff + act2 * 0.3f + bias[(size_t)c * NN + ncol]
                           + g_boost[(size_t)c * NN + ncol];
            __syncwarp();
        }
        if (lane < mcnt) {
            float v = s_be[w][lane];
            int g = 0;
            for (int j = 0; j < mcnt; j++) g += (s_be[w][j] > v) ? 1 : 0;
            s_bf[w][lane] = (g < r) ? 1 : 0;
        }
        __syncwarp();
        #pragma unroll
        for (int s = 0; s < 16; s++) {
            bool isb = (bpos[s] >= 0);
            win[s] = (bf[s] > thi) || (isb && s_bf[w][bpos[s]]);
        }
    }

    float lsum = 0.f;
    #pragma unroll
    for (int s = 0; s < 16; s++) {
        float rl = fmaxf(f[s], 0.f);
        lsum += win[s] ? rl : 0.f;
    }
    #pragma unroll
    for (int o = 16; o; o >>= 1) lsum += __shfl_xor_sync(0xffffffffu, lsum, o);
    float scale = (float)k / (lsum + 1e-8f);

    float4* orow = reinterpret_cast<float4*>(act + (size_t)row * NN);
    int cnt_total = 0;
    #pragma unroll
    for (int i = 0; i < 4; i++) {
        float ov[4];
        #pragma unroll
        for (int q = 0; q < 4; q++) {
            int s = i * 4 + q;
            float rl  = fmaxf(f[s], 0.f);
            float val = win[s] ? rl * scale : 0.f;
            ov[q] = val;
            bool put = win[s] && (rl > 0.f);
            unsigned m = __ballot_sync(0xffffffffu, put);
            if (put) {
                int pos = cnt_total + __popc(m & ((1u << lane) - 1u));
                if (pos < 64) {
                    s_ii[w][pos] = i * 128 + lane * 4 + q;
                    s_vv[w][pos] = val;
                }
            }
            cnt_total += __popc(m);
        }
        orow[i * 32 + lane] = make_float4(ov[0], ov[1], ov[2], ov[3]);
    }
    if (cnt_total > 64) cnt_total = 64;
    __syncwarp();

    const float* WpC = Wp + (size_t)c * NN * DD;
    float4 acc0 = make_float4(0.f, 0.f, 0.f, 0.f);
    float4 acc1 = make_float4(0.f, 0.f, 0.f, 0.f);
    for (int j = 0; j < cnt_total; j++) {
        float vj = s_vv[w][j];
        const float4* wr = reinterpret_cast<const float4*>(WpC + (size_t)s_ii[w][j] * DD);
        float4 w0 = wr[lane];
        float4 w1 = wr[lane + 32];
        acc0.x = fmaf(vj, w0.x, acc0.x); acc0.y = fmaf(vj, w0.y, acc0.y);
        acc0.z = fmaf(vj, w0.z, acc0.z); acc0.w = fmaf(vj, w0.w, acc0.w);
        acc1.x = fmaf(vj, w1.x, acc1.x); acc1.y = fmaf(vj, w1.y, acc1.y);
        acc1.z = fmaf(vj, w1.z, acc1.z); acc1.w = fmaf(vj, w1.w, acc1.w);
    }

    const float4* xr = reinterpret_cast<const float4*>(x_in + (size_t)b * DD);
    float4 x0 = xr[lane], x1 = xr[lane + 32];
    float4* prow = reinterpret_cast<float4*>(pred + (size_t)row * DD);
    float4* erow = reinterpret_cast<float4*>(err  + (size_t)row * DD);
    prow[lane]      = acc0;
    prow[lane + 32] = acc1;
    erow[lane]      = make_float4(x0.x - acc0.x, x0.y - acc0.y, x0.z - acc0.z, x0.w - acc0.w);
    erow[lane + 32] = make_float4(x1.x - acc1.x, x1.y - acc1.y, x1.z - acc1.z, x1.w - acc1.w);
}

// ---------------------------------------------------------------------------
extern "C" void kernel_launch(void* const* d_in, const int* in_sizes, int n_in,
                              void* d_out, int out_size)
{
    const float* x_in  = (const float*)d_in[0];
    const float* x_ctx = (const float*)d_in[1];
    const float* Wff   = (const float*)d_in[2];
    const float* Wctx  = (const float*)d_in[3];
    const float* Wpred = (const float*)d_in[4];
    const float* bias  = (const float*)d_in[5];
    const float* avg   = (const float*)d_in[6];
    const int*   kptr  = (const int*)d_in[7];

    float* act  = (float*)d_out;                              // [B,C,N]
    float* pred = act  + (size_t)BB * CC * NN;                // [B,C,D]
    float* err  = pred + (size_t)BB * CC * DD;                // [B,C,D]

    boost_kernel<<<(CC * NN + 255) / 256, 256>>>(avg);

    dim3 g1(NN / 128, BB / 128, CC);
    drive_gemm<<<g1, 256>>>(x_in, x_ctx, Wff, Wctx, bias, act);

    topk_pred<<<BB * CC / 8, 256>>>(kptr, x_in, x_ctx, Wff, Wctx, bias,
                                    Wpred, act, pred, err);
}